// round 12
// baseline (speedup 1.0000x reference)
#include <cuda_runtime.h>
#include <math.h>

#define NB 64
#define NT 512
#define NC 768
#define NH 192
#define ROT 32
#define M_TOT (NB*NT)

// Scratch for projected q, k, v (device globals: no allocation at launch time)
__device__ float g_q[M_TOT * NH];
__device__ float g_k[M_TOT * NH];
__device__ float g_v[M_TOT * NH];

// ============================================================================
// helpers
// ============================================================================
__device__ __forceinline__ float f2tf32(float x) {
    unsigned u;
    asm("cvt.rna.tf32.f32 %0, %1;" : "=r"(u) : "f"(x));
    return __uint_as_float(u);
}
__device__ __forceinline__ float4 f2tf32_4(float4 v) {
    return make_float4(f2tf32(v.x), f2tf32(v.y), f2tf32(v.z), f2tf32(v.w));
}
__device__ __forceinline__ float fast_ex2(float x) {
    float y;
    asm("ex2.approx.ftz.f32 %0, %1;" : "=f"(y) : "f"(x));
    return y;
}
#define L2E 1.4426950408889634f

#define MMA_TF32(c0, c1, c2, c3, a0, a1, a2, a3, b0, b1) \
    asm volatile( \
        "mma.sync.aligned.m16n8k8.row.col.f32.tf32.tf32.f32 " \
        "{%0,%1,%2,%3}, {%4,%5,%6,%7}, {%8,%9}, {%0,%1,%2,%3};\n" \
        : "+f"(c0), "+f"(c1), "+f"(c2), "+f"(c3) \
        : "r"(a0), "r"(a1), "r"(a2), "r"(a3), "r"(b0), "r"(b1))

// ============================================================================
// QKV projection: out = X(32768,768) @ W(768,192), RoPE fused for q,k.
// tf32 mma.sync.m16n8k8. Block tile 64x192 (full N), BK=16, 256 threads
// (8 warps as 2Mx4N, warp tile 32x48). Double-buffered smem, 1 sync/tile.
// (Unchanged from R10 win.)
// ============================================================================
#define GBM 64
#define GBK 16
#define LDA 20    // As row stride: frag banks (20*row + t) mod 32, unique per warp phase
#define LDB 200   // Bs row stride: frag banks (8t + g), unique (200 mod 32 = 8)
#define ASZ (GBM * LDA)    // 1280 floats
#define BSZ (GBK * LDB)    // 3200 floats

__global__ __launch_bounds__(256)
void qkv_mma(const float* __restrict__ X,
             const float* __restrict__ Wq,
             const float* __restrict__ Wk,
             const float* __restrict__ Wv)
{
    __shared__ float As[2][ASZ];   // [m][k] m-major
    __shared__ float Bs[2][BSZ];   // [k][n] k-major

    const int which = blockIdx.y;
    const float* W  = (which == 0) ? Wq : (which == 1) ? Wk : Wv;
    float* outp     = (which == 0) ? g_q : (which == 1) ? g_k : g_v;
    const bool rope = (which < 2);

    const int m0 = blockIdx.x * GBM;

    const int tid  = threadIdx.x;
    const int lane = tid & 31;
    const int wid  = tid >> 5;
    const int wm   = (wid & 1) * 32;    // warp M offset
    const int wn   = (wid >> 1) * 48;   // warp N offset
    const int g    = lane >> 2;
    const int t    = lane & 3;

    const int am = tid >> 2;            // 0..63
    const int ak = (tid & 3) * 4;       // 0,4,8,12
    const float* Ag = X + (size_t)(m0 + am) * NC + ak;

    int brow[3], bcol[3];
    #pragma unroll
    for (int j = 0; j < 3; j++) {
        int e = tid + j * 256;          // 0..767
        brow[j] = e / 48;               // 0..15 (k)
        bcol[j] = (e - brow[j] * 48) * 4;  // 0..188
    }

    float4 ra;
    float4 rb[3];

    float c[2][6][4];
    #pragma unroll
    for (int mi = 0; mi < 2; mi++)
        #pragma unroll
        for (int ni = 0; ni < 6; ni++)
            #pragma unroll
            for (int r = 0; r < 4; r++) c[mi][ni][r] = 0.f;

    const int K_TILES = NC / GBK;   // 48

    ra = *(const float4*)(Ag);
    #pragma unroll
    for (int j = 0; j < 3; j++)
        rb[j] = *(const float4*)(W + (size_t)brow[j] * NH + bcol[j]);
    *(float4*)&As[0][am * LDA + ak] = f2tf32_4(ra);
    #pragma unroll
    for (int j = 0; j < 3; j++)
        *(float4*)&Bs[0][brow[j] * LDB + bcol[j]] = f2tf32_4(rb[j]);
    __syncthreads();

    for (int kt = 0; kt < K_TILES; kt++) {
        const int cur = kt & 1;
        const bool more = (kt + 1 < K_TILES);
        if (more) {
            int k0 = (kt + 1) * GBK;
            ra = *(const float4*)(Ag + k0);
            #pragma unroll
            for (int j = 0; j < 3; j++)
                rb[j] = *(const float4*)(W + (size_t)(k0 + brow[j]) * NH + bcol[j]);
        }

        const float* Ac = As[cur];
        const float* Bc = Bs[cur];
        #pragma unroll
        for (int ks = 0; ks < GBK; ks += 8) {
            unsigned af[2][4];
            unsigned bf[6][2];
            #pragma unroll
            for (int mi = 0; mi < 2; mi++) {
                int r0 = (wm + mi * 16 + g) * LDA + ks + t;
                int r1 = (wm + mi * 16 + 8 + g) * LDA + ks + t;
                af[mi][0] = __float_as_uint(Ac[r0]);
                af[mi][1] = __float_as_uint(Ac[r1]);
                af[mi][2] = __float_as_uint(Ac[r0 + 4]);
                af[mi][3] = __float_as_uint(Ac[r1 + 4]);
            }
            #pragma unroll
            for (int ni = 0; ni < 6; ni++) {
                int col = wn + ni * 8 + g;
                bf[ni][0] = __float_as_uint(Bc[(ks + t) * LDB + col]);
                bf[ni][1] = __float_as_uint(Bc[(ks + t + 4) * LDB + col]);
            }
            #pragma unroll
            for (int mi = 0; mi < 2; mi++)
                #pragma unroll
                for (int ni = 0; ni < 6; ni++)
                    MMA_TF32(c[mi][ni][0], c[mi][ni][1], c[mi][ni][2], c[mi][ni][3],
                             af[mi][0], af[mi][1], af[mi][2], af[mi][3],
                             bf[ni][0], bf[ni][1]);
        }

        if (more) {
            const int nxt = cur ^ 1;
            *(float4*)&As[nxt][am * LDA + ak] = f2tf32_4(ra);
            #pragma unroll
            for (int j = 0; j < 3; j++)
                *(float4*)&Bs[nxt][brow[j] * LDB + bcol[j]] = f2tf32_4(rb[j]);
            __syncthreads();
        }
    }

    const float LOG2_THETA = 13.287712379549449f;

    #pragma unroll
    for (int mi = 0; mi < 2; mi++) {
        #pragma unroll
        for (int ni = 0; ni < 6; ni++) {
            int col = wn + ni * 8 + t * 2;
            #pragma unroll
            for (int half = 0; half < 2; half++) {
                int row = m0 + wm + mi * 16 + g + half * 8;
                float x1 = c[mi][ni][half * 2 + 0];
                float x2 = c[mi][ni][half * 2 + 1];
                if (rope && col < ROT) {
                    int jh = col >> 1;
                    int tpos = row & (NT - 1);
                    float inv = exp2f(-(float)(2 * jh) * (1.0f / 32.0f) * LOG2_THETA);
                    float ang = (float)tpos * inv;
                    float sn, cs;
                    sincosf(ang, &sn, &cs);
                    float r1 = x1 * cs - x2 * sn;
                    float r2 = x2 * cs + x1 * sn;
                    x1 = r1; x2 = r2;
                }
                *(float2*)&outp[(size_t)row * NH + col] = make_float2(x1, x2);
            }
        }
    }
}

// ============================================================================
// Tensor-core flash attention (tf32 mma for S=QK^T and O=PV).
// Block = (batch b, query tile of 64 rows). 512 threads = 16 warps.
// S: warp grid 4Mx4N, warp tile 16x16. PV: warp tile 16x48.
// ============================================================================
#define BQ  64
#define BKT 64
#define LDQ 196  // Q/K smem row stride (floats): frag bank = 4*row+t, unique
#define LDV 200  // V smem row stride: frag bank = 8*t+g, unique
#define LDS 68   // S smem row stride: frag bank = 4*row+t, unique

#define ATTN_SMEM_FLOATS (BQ*LDQ + BKT*LDQ + BKT*LDV + BQ*LDS + 3*BQ)

__global__ __launch_bounds__(512)
void attn_mma(float* __restrict__ out)
{
    extern __shared__ float sm[];
    float* Qs  = sm;                  // [64][LDQ]
    float* Ks  = Qs  + BQ * LDQ;      // [64][LDQ]  natural row-major
    float* Vs  = Ks  + BKT * LDQ;     // [64][LDV]  natural row-major
    float* Ss  = Vs  + BKT * LDV;     // [64][LDS]
    float* m_s = Ss  + BQ * LDS;      // [64]
    float* l_s = m_s + BQ;            // [64]
    float* c_s = l_s + BQ;            // [64]

    const int b   = blockIdx.y;
    const int qt  = gridDim.x - 1 - blockIdx.x;   // heavy tiles first
    const int q0  = qt * BQ;
    const int tid = threadIdx.x;
    const int lane = tid & 31;
    const int wid  = tid >> 5;        // 0..15
    const int g    = lane >> 2;       // 0..7
    const int t    = lane & 3;        // 0..3
    const int wm   = (wid & 3) * 16;  // warp M offset (rows)
    const int wns  = (wid >> 2) * 16; // warp N offset for S (16 cols/warp)
    const int wnv  = (wid >> 2) * 48; // warp N offset for PV / O (48 cols/warp)

    // ---- load Q tile (tf32-rounded): 3072 float4 / 512 threads = 6 each ----
    {
        const float4* src = (const float4*)(g_q + ((size_t)b * NT + q0) * NH);
        #pragma unroll
        for (int i = 0; i < 6; i++) {
            int e = tid + i * 512;          // 0..3071
            int row = e / 48, c4 = e - row * 48;
            float4 v = src[e];
            *(float4*)&Qs[row * LDQ + c4 * 4] = f2tf32_4(v);
        }
    }
    if (tid < BQ) { m_s[tid] = -INFINITY; l_s[tid] = 0.f; }

    float o[6][4];
    #pragma unroll
    for (int ni = 0; ni < 6; ni++)
        #pragma unroll
        for (int r = 0; r < 4; r++) o[ni][r] = 0.f;

    const float scale = 1.0f / sqrtf((float)NH);

    for (int kt = 0; kt <= qt; kt++) {
        __syncthreads();   // prev PV done before K/V/S overwrite

        // ---- load K, V tiles (tf32-rounded) ----
        {
            const float4* ksrc = (const float4*)(g_k + ((size_t)b * NT + kt * BKT) * NH);
            const float4* vsrc = (const float4*)(g_v + ((size_t)b * NT + kt * BKT) * NH);
            #pragma unroll
            for (int i = 0; i < 6; i++) {
                int e = tid + i * 512;
                int row = e / 48, c4 = e - row * 48;
                float4 kv = ksrc[e];
                *(float4*)&Ks[row * LDQ + c4 * 4] = f2tf32_4(kv);
                float4 vv = vsrc[e];
                *(float4*)&Vs[row * LDV + c4 * 4] = f2tf32_4(vv);
            }
        }
        __syncthreads();

        // ---- S = Q K^T via mma (each warp: 16 rows x 16 cols) ----
        float s[2][4];
        #pragma unroll
        for (int ni = 0; ni < 2; ni++)
            #pragma unroll
            for (int r = 0; r < 4; r++) s[ni][r] = 0.f;

        #pragma unroll 4
        for (int ks = 0; ks < NH; ks += 8) {
            unsigned af[4];
            int r0 = (wm + g) * LDQ + ks + t;
            int r1 = (wm + 8 + g) * LDQ + ks + t;
            af[0] = __float_as_uint(Qs[r0]);
            af[1] = __float_as_uint(Qs[r1]);
            af[2] = __float_as_uint(Qs[r0 + 4]);
            af[3] = __float_as_uint(Qs[r1 + 4]);
            #pragma unroll
            for (int ni = 0; ni < 2; ni++) {
                int col = wns + ni * 8 + g;
                unsigned b0 = __float_as_uint(Ks[col * LDQ + ks + t]);
                unsigned b1 = __float_as_uint(Ks[col * LDQ + ks + t + 4]);
                MMA_TF32(s[ni][0], s[ni][1], s[ni][2], s[ni][3],
                         af[0], af[1], af[2], af[3], b0, b1);
            }
        }

        // ---- scale + causal mask, write S to smem ----
        const bool diag = (kt == qt);
        #pragma unroll
        for (int ni = 0; ni < 2; ni++) {
            #pragma unroll
            for (int half = 0; half < 2; half++) {
                int row = wm + half * 8 + g;
                #pragma unroll
                for (int j = 0; j < 2; j++) {
                    int col = wns + ni * 8 + t * 2 + j;
                    float v = s[ni][half * 2 + j] * scale;
                    if (diag && col > row) v = -INFINITY;
                    Ss[row * LDS + col] = v;
                }
            }
        }
        __syncthreads();

        // ---- online softmax: 8 threads per row, 8 cols each ----
        {
            int r   = tid >> 3;         // 0..63
            int sub = tid & 7;          // 0..7
            float* rp = Ss + r * LDS + sub * 8;

            float p[8];
            *(float4*)(p + 0) = *(float4*)(rp + 0);
            *(float4*)(p + 4) = *(float4*)(rp + 4);

            float tmax = p[0];
            #pragma unroll
            for (int i = 1; i < 8; i++) tmax = fmaxf(tmax, p[i]);
            tmax = fmaxf(tmax, __shfl_xor_sync(0xffffffffu, tmax, 1));
            tmax = fmaxf(tmax, __shfl_xor_sync(0xffffffffu, tmax, 2));
            tmax = fmaxf(tmax, __shfl_xor_sync(0xffffffffu, tmax, 4));

            float mo   = m_s[r];
            float rmax = fmaxf(mo, tmax);
            float corr = fast_ex2((mo - rmax) * L2E);

            float sum = 0.f;
            #pragma unroll
            for (int i = 0; i < 8; i++) {
                float e = fast_ex2((p[i] - rmax) * L2E);
                sum += e;
                p[i] = f2tf32(e);
            }
            *(float4*)(rp + 0) = *(float4*)(p + 0);
            *(float4*)(rp + 4) = *(float4*)(p + 4);

            sum += __shfl_xor_sync(0xffffffffu, sum, 1);
            sum += __shfl_xor_sync(0xffffffffu, sum, 2);
            sum += __shfl_xor_sync(0xffffffffu, sum, 4);
            if (sub == 0) {
                l_s[r] = l_s[r] * corr + sum;
                m_s[r] = rmax;
                c_s[r] = corr;
            }
        }
        __syncthreads();

        // ---- O = O*corr + P V via mma (each warp: 16 rows x 48 cols) ----
        {
            float corr0 = c_s[wm + g];
            float corr1 = c_s[wm + 8 + g];
            #pragma unroll
            for (int ni = 0; ni < 6; ni++) {
                o[ni][0] *= corr0; o[ni][1] *= corr0;
                o[ni][2] *= corr1; o[ni][3] *= corr1;
            }
        }
        #pragma unroll
        for (int kk = 0; kk < BKT; kk += 8) {
            unsigned af[4];
            int r0 = (wm + g) * LDS + kk + t;
            int r1 = (wm + 8 + g) * LDS + kk + t;
            af[0] = __float_as_uint(Ss[r0]);
            af[1] = __float_as_uint(Ss[r1]);
            af[2] = __float_as_uint(Ss[r0 + 4]);
            af[3] = __float_as_uint(Ss[r1 + 4]);
            #pragma unroll
            for (int ni = 0; ni < 6; ni++) {
                int col = wnv + ni * 8 + g;
                unsigned b0 = __float_as_uint(Vs[(kk + t) * LDV + col]);
                unsigned b1 = __float_as_uint(Vs[(kk + t + 4) * LDV + col]);
                MMA_TF32(o[ni][0], o[ni][1], o[ni][2], o[ni][3],
                         af[0], af[1], af[2], af[3], b0, b1);
            }
        }
    }

    // ---- finalize: O / l, store ----
    __syncthreads();
    {
        float inv0 = 1.0f / l_s[wm + g];
        float inv1 = 1.0f / l_s[wm + 8 + g];
        float* ob = out + ((size_t)b * NT + q0) * NH;
        #pragma unroll
        for (int ni = 0; ni < 6; ni++) {
            int col = wnv + ni * 8 + t * 2;
            int row0 = wm + g;
            int row1 = wm + 8 + g;
            *(float2*)&ob[(size_t)row0 * NH + col] =
                make_float2(o[ni][0] * inv0, o[ni][1] * inv0);
            *(float2*)&ob[(size_t)row1 * NH + col] =
                make_float2(o[ni][2] * inv1, o[ni][3] * inv1);
        }
    }
}

// ============================================================================
// Launch
// ============================================================================
extern "C" void kernel_launch(void* const* d_in, const int* in_sizes, int n_in,
                              void* d_out, int out_size)
{
    const float* x  = (const float*)d_in[0];
    const float* Wq = (const float*)d_in[1];
    const float* Wk = (const float*)d_in[2];
    const float* Wv = (const float*)d_in[3];
    float* out = (float*)d_out;

    (void)in_sizes; (void)n_in; (void)out_size;

    // QKV projections (full-N 64x192 tile, tf32 mma)
    dim3 ggrd(M_TOT / GBM, 3);      // (512, 3)
    qkv_mma<<<ggrd, 256>>>(x, Wq, Wk, Wv);

    // Attention (512 threads / 16 warps per block)
    size_t smem = ATTN_SMEM_FLOATS * sizeof(float);
    cudaFuncSetAttribute(attn_mma, cudaFuncAttributeMaxDynamicSharedMemorySize, (int)smem);
    dim3 agrd(NT / BQ, NB);         // (8, 64)
    attn_mma<<<agrd, 512, smem>>>(out);
}

// round 13
// speedup vs baseline: 1.5183x; 1.5183x over previous
#include <cuda_runtime.h>
#include <math.h>

#define NB 64
#define NT 512
#define NC 768
#define NH 192
#define ROT 32
#define M_TOT (NB*NT)

// Scratch for projected q, k, v (device globals: no allocation at launch time)
__device__ float g_q[M_TOT * NH];
__device__ float g_k[M_TOT * NH];
__device__ float g_v[M_TOT * NH];

// ============================================================================
// helpers
// ============================================================================
__device__ __forceinline__ float f2tf32(float x) {
    unsigned u;
    asm("cvt.rna.tf32.f32 %0, %1;" : "=r"(u) : "f"(x));
    return __uint_as_float(u);
}
__device__ __forceinline__ float4 f2tf32_4(float4 v) {
    return make_float4(f2tf32(v.x), f2tf32(v.y), f2tf32(v.z), f2tf32(v.w));
}
__device__ __forceinline__ float fast_ex2(float x) {
    float y;
    asm("ex2.approx.ftz.f32 %0, %1;" : "=f"(y) : "f"(x));
    return y;
}
#define L2E 1.4426950408889634f

#define LDSM4(r0, r1, r2, r3, addr) \
    asm volatile("ldmatrix.sync.aligned.m8n8.x4.shared.b16 {%0,%1,%2,%3}, [%4];" \
                 : "=r"(r0), "=r"(r1), "=r"(r2), "=r"(r3) : "r"(addr))

#define MMA_TF32(c0, c1, c2, c3, a0, a1, a2, a3, b0, b1) \
    asm volatile( \
        "mma.sync.aligned.m16n8k8.row.col.f32.tf32.tf32.f32 " \
        "{%0,%1,%2,%3}, {%4,%5,%6,%7}, {%8,%9}, {%0,%1,%2,%3};\n" \
        : "+f"(c0), "+f"(c1), "+f"(c2), "+f"(c3) \
        : "r"(a0), "r"(a1), "r"(a2), "r"(a3), "r"(b0), "r"(b1))

// ============================================================================
// QKV projection: out = X(32768,768) @ W(768,192), RoPE fused for q,k.
// tf32 mma.sync.m16n8k8. Block tile 64x192 (full N), BK=16, 256 threads
// (8 warps as 2Mx4N, warp tile 32x48). Double-buffered smem, 1 sync/tile.
// A fragments via ldmatrix.x4 (pattern validated in R8); B scalar, k-major.
// ============================================================================
#define GBM 64
#define GBK 16
#define LDA 20    // As row stride: LDSM phase banks (4*row + col) mod 32 unique
#define LDB 200   // Bs row stride: frag banks (8t + g), unique (200 mod 32 = 8)
#define ASZ (GBM * LDA)    // 1280 floats
#define BSZ (GBK * LDB)    // 3200 floats

__global__ __launch_bounds__(256)
void qkv_mma(const float* __restrict__ X,
             const float* __restrict__ Wq,
             const float* __restrict__ Wk,
             const float* __restrict__ Wv)
{
    __shared__ float As[2][ASZ];   // [m][k] m-major
    __shared__ float Bs[2][BSZ];   // [k][n] k-major

    const int which = blockIdx.y;
    const float* W  = (which == 0) ? Wq : (which == 1) ? Wk : Wv;
    float* outp     = (which == 0) ? g_q : (which == 1) ? g_k : g_v;
    const bool rope = (which < 2);

    const int m0 = blockIdx.x * GBM;

    const int tid  = threadIdx.x;
    const int lane = tid & 31;
    const int wid  = tid >> 5;
    const int wm   = (wid & 1) * 32;    // warp M offset
    const int wn   = (wid >> 1) * 48;   // warp N offset
    const int g    = lane >> 2;
    const int t    = lane & 3;

    const int am = tid >> 2;            // 0..63
    const int ak = (tid & 3) * 4;       // 0,4,8,12
    const float* Ag = X + (size_t)(m0 + am) * NC + ak;

    int brow[3], bcol[3];
    #pragma unroll
    for (int j = 0; j < 3; j++) {
        int e = tid + j * 256;          // 0..767
        brow[j] = e / 48;               // 0..15 (k)
        bcol[j] = (e - brow[j] * 48) * 4;  // 0..188
    }

    // LDSM base addresses for A fragments (byte offsets into As[0])
    const unsigned sA = (unsigned)__cvta_generic_to_shared(&As[0][0]);
    unsigned a_addr[2];
    #pragma unroll
    for (int mi = 0; mi < 2; mi++) {
        int rowA = wm + mi * 16 + (lane & 15);
        int colA = (lane >> 4) * 4;
        a_addr[mi] = sA + (unsigned)(rowA * LDA + colA) * 4u;
    }

    float4 ra;
    float4 rb[3];

    float c[2][6][4];
    #pragma unroll
    for (int mi = 0; mi < 2; mi++)
        #pragma unroll
        for (int ni = 0; ni < 6; ni++)
            #pragma unroll
            for (int r = 0; r < 4; r++) c[mi][ni][r] = 0.f;

    const int K_TILES = NC / GBK;   // 48

    ra = *(const float4*)(Ag);
    #pragma unroll
    for (int j = 0; j < 3; j++)
        rb[j] = *(const float4*)(W + (size_t)brow[j] * NH + bcol[j]);
    *(float4*)&As[0][am * LDA + ak] = f2tf32_4(ra);
    #pragma unroll
    for (int j = 0; j < 3; j++)
        *(float4*)&Bs[0][brow[j] * LDB + bcol[j]] = f2tf32_4(rb[j]);
    __syncthreads();

    for (int kt = 0; kt < K_TILES; kt++) {
        const int cur = kt & 1;
        const bool more = (kt + 1 < K_TILES);
        if (more) {
            int k0 = (kt + 1) * GBK;
            ra = *(const float4*)(Ag + k0);
            #pragma unroll
            for (int j = 0; j < 3; j++)
                rb[j] = *(const float4*)(W + (size_t)(k0 + brow[j]) * NH + bcol[j]);
        }

        const unsigned abuf = cur ? (unsigned)(ASZ * 4) : 0u;
        const float* Bc = Bs[cur];
        #pragma unroll
        for (int ks = 0; ks < GBK; ks += 8) {
            unsigned af[2][4];
            unsigned bf[6][2];
            #pragma unroll
            for (int mi = 0; mi < 2; mi++)
                LDSM4(af[mi][0], af[mi][1], af[mi][2], af[mi][3],
                      a_addr[mi] + abuf + (unsigned)ks * 4u);
            #pragma unroll
            for (int ni = 0; ni < 6; ni++) {
                int col = wn + ni * 8 + g;
                bf[ni][0] = __float_as_uint(Bc[(ks + t) * LDB + col]);
                bf[ni][1] = __float_as_uint(Bc[(ks + t + 4) * LDB + col]);
            }
            #pragma unroll
            for (int mi = 0; mi < 2; mi++)
                #pragma unroll
                for (int ni = 0; ni < 6; ni++)
                    MMA_TF32(c[mi][ni][0], c[mi][ni][1], c[mi][ni][2], c[mi][ni][3],
                             af[mi][0], af[mi][1], af[mi][2], af[mi][3],
                             bf[ni][0], bf[ni][1]);
        }

        if (more) {
            const int nxt = cur ^ 1;
            *(float4*)&As[nxt][am * LDA + ak] = f2tf32_4(ra);
            #pragma unroll
            for (int j = 0; j < 3; j++)
                *(float4*)&Bs[nxt][brow[j] * LDB + bcol[j]] = f2tf32_4(rb[j]);
            __syncthreads();
        }
    }

    const float LOG2_THETA = 13.287712379549449f;

    #pragma unroll
    for (int mi = 0; mi < 2; mi++) {
        #pragma unroll
        for (int ni = 0; ni < 6; ni++) {
            int col = wn + ni * 8 + t * 2;
            #pragma unroll
            for (int half = 0; half < 2; half++) {
                int row = m0 + wm + mi * 16 + g + half * 8;
                float x1 = c[mi][ni][half * 2 + 0];
                float x2 = c[mi][ni][half * 2 + 1];
                if (rope && col < ROT) {
                    int jh = col >> 1;
                    int tpos = row & (NT - 1);
                    float inv = exp2f(-(float)(2 * jh) * (1.0f / 32.0f) * LOG2_THETA);
                    float ang = (float)tpos * inv;
                    float sn, cs;
                    sincosf(ang, &sn, &cs);
                    float r1 = x1 * cs - x2 * sn;
                    float r2 = x2 * cs + x1 * sn;
                    x1 = r1; x2 = r2;
                }
                *(float2*)&outp[(size_t)row * NH + col] = make_float2(x1, x2);
            }
        }
    }
}

// ============================================================================
// Tensor-core flash attention (tf32 mma for S=QK^T and O=PV).
// Block = (batch b, query tile of 64 rows). 256 threads = 8 warps.
// (Exact R10 winner configuration.)
// ============================================================================
#define BQ  64
#define BKT 64
#define LDQ 196  // Q/K smem row stride (floats): frag bank = 4*row+t, unique
#define LDV 200  // V smem row stride: frag bank = 8*t+g, unique
#define LDS 68   // S smem row stride: frag bank = 4*row+t, unique

#define ATTN_SMEM_FLOATS (BQ*LDQ + BKT*LDQ + BKT*LDV + BQ*LDS + 3*BQ)

__global__ __launch_bounds__(256)
void attn_mma(float* __restrict__ out)
{
    extern __shared__ float sm[];
    float* Qs  = sm;                  // [64][LDQ]
    float* Ks  = Qs  + BQ * LDQ;      // [64][LDQ]  natural row-major
    float* Vs  = Ks  + BKT * LDQ;     // [64][LDV]  natural row-major
    float* Ss  = Vs  + BKT * LDV;     // [64][LDS]
    float* m_s = Ss  + BQ * LDS;      // [64]
    float* l_s = m_s + BQ;            // [64]
    float* c_s = l_s + BQ;            // [64]

    const int b   = blockIdx.y;
    const int qt  = gridDim.x - 1 - blockIdx.x;   // heavy tiles first
    const int q0  = qt * BQ;
    const int tid = threadIdx.x;
    const int lane = tid & 31;
    const int wid  = tid >> 5;
    const int g    = lane >> 2;       // 0..7
    const int t    = lane & 3;        // 0..3
    const int wm   = (wid & 3) * 16;  // warp M offset (rows)
    const int wns  = (wid >> 2) * 32; // warp N offset for S
    const int wnv  = (wid >> 2) * 96; // warp N offset for PV / O

    // ---- load Q tile (tf32-rounded) ----
    {
        const float4* src = (const float4*)(g_q + ((size_t)b * NT + q0) * NH);
        #pragma unroll
        for (int i = 0; i < 12; i++) {
            int e = tid + i * 256;          // 0..3071 float4s
            int row = e / 48, c4 = e - row * 48;
            float4 v = src[e];
            *(float4*)&Qs[row * LDQ + c4 * 4] = f2tf32_4(v);
        }
    }
    if (tid < BQ) { m_s[tid] = -INFINITY; l_s[tid] = 0.f; }

    float o[12][4];
    #pragma unroll
    for (int ni = 0; ni < 12; ni++)
        #pragma unroll
        for (int r = 0; r < 4; r++) o[ni][r] = 0.f;

    const float scale = 1.0f / sqrtf((float)NH);

    for (int kt = 0; kt <= qt; kt++) {
        __syncthreads();   // prev PV done before K/V/S overwrite

        // ---- load K, V tiles (tf32-rounded) ----
        {
            const float4* ksrc = (const float4*)(g_k + ((size_t)b * NT + kt * BKT) * NH);
            const float4* vsrc = (const float4*)(g_v + ((size_t)b * NT + kt * BKT) * NH);
            #pragma unroll
            for (int i = 0; i < 12; i++) {
                int e = tid + i * 256;
                int row = e / 48, c4 = e - row * 48;
                float4 kv = ksrc[e];
                *(float4*)&Ks[row * LDQ + c4 * 4] = f2tf32_4(kv);
                float4 vv = vsrc[e];
                *(float4*)&Vs[row * LDV + c4 * 4] = f2tf32_4(vv);
            }
        }
        __syncthreads();

        // ---- S = Q K^T via mma (each warp: 16 rows x 32 cols) ----
        float s[4][4];
        #pragma unroll
        for (int ni = 0; ni < 4; ni++)
            #pragma unroll
            for (int r = 0; r < 4; r++) s[ni][r] = 0.f;

        #pragma unroll 4
        for (int ks = 0; ks < NH; ks += 8) {
            unsigned af[4];
            int r0 = (wm + g) * LDQ + ks + t;
            int r1 = (wm + 8 + g) * LDQ + ks + t;
            af[0] = __float_as_uint(Qs[r0]);
            af[1] = __float_as_uint(Qs[r1]);
            af[2] = __float_as_uint(Qs[r0 + 4]);
            af[3] = __float_as_uint(Qs[r1 + 4]);
            #pragma unroll
            for (int ni = 0; ni < 4; ni++) {
                int col = wns + ni * 8 + g;
                unsigned b0 = __float_as_uint(Ks[col * LDQ + ks + t]);
                unsigned b1 = __float_as_uint(Ks[col * LDQ + ks + t + 4]);
                MMA_TF32(s[ni][0], s[ni][1], s[ni][2], s[ni][3],
                         af[0], af[1], af[2], af[3], b0, b1);
            }
        }

        // ---- scale + causal mask, write S to smem ----
        const bool diag = (kt == qt);
        #pragma unroll
        for (int ni = 0; ni < 4; ni++) {
            #pragma unroll
            for (int half = 0; half < 2; half++) {
                int row = wm + half * 8 + g;
                #pragma unroll
                for (int j = 0; j < 2; j++) {
                    int col = wns + ni * 8 + t * 2 + j;
                    float v = s[ni][half * 2 + j] * scale;
                    if (diag && col > row) v = -INFINITY;
                    Ss[row * LDS + col] = v;
                }
            }
        }
        __syncthreads();

        // ---- online softmax: 4 threads per row, 16 cols each ----
        {
            int r   = tid >> 2;
            int sub = tid & 3;
            float* rp = Ss + r * LDS + sub * 16;

            float p[16];
            *(float4*)(p + 0)  = *(float4*)(rp + 0);
            *(float4*)(p + 4)  = *(float4*)(rp + 4);
            *(float4*)(p + 8)  = *(float4*)(rp + 8);
            *(float4*)(p + 12) = *(float4*)(rp + 12);

            float tmax = p[0];
            #pragma unroll
            for (int i = 1; i < 16; i++) tmax = fmaxf(tmax, p[i]);
            tmax = fmaxf(tmax, __shfl_xor_sync(0xffffffffu, tmax, 1));
            tmax = fmaxf(tmax, __shfl_xor_sync(0xffffffffu, tmax, 2));

            float mo   = m_s[r];
            float rmax = fmaxf(mo, tmax);
            float corr = fast_ex2((mo - rmax) * L2E);

            float sum = 0.f;
            #pragma unroll
            for (int i = 0; i < 16; i++) {
                float e = fast_ex2((p[i] - rmax) * L2E);
                sum += e;
                p[i] = f2tf32(e);
            }
            *(float4*)(rp + 0)  = *(float4*)(p + 0);
            *(float4*)(rp + 4)  = *(float4*)(p + 4);
            *(float4*)(rp + 8)  = *(float4*)(p + 8);
            *(float4*)(rp + 12) = *(float4*)(p + 12);

            sum += __shfl_xor_sync(0xffffffffu, sum, 1);
            sum += __shfl_xor_sync(0xffffffffu, sum, 2);
            if (sub == 0) {
                l_s[r] = l_s[r] * corr + sum;
                m_s[r] = rmax;
                c_s[r] = corr;
            }
        }
        __syncthreads();

        // ---- O = O*corr + P V via mma (each warp: 16 rows x 96 cols) ----
        {
            float corr0 = c_s[wm + g];
            float corr1 = c_s[wm + 8 + g];
            #pragma unroll
            for (int ni = 0; ni < 12; ni++) {
                o[ni][0] *= corr0; o[ni][1] *= corr0;
                o[ni][2] *= corr1; o[ni][3] *= corr1;
            }
        }
        #pragma unroll
        for (int kk = 0; kk < BKT; kk += 8) {
            unsigned af[4];
            int r0 = (wm + g) * LDS + kk + t;
            int r1 = (wm + 8 + g) * LDS + kk + t;
            af[0] = __float_as_uint(Ss[r0]);
            af[1] = __float_as_uint(Ss[r1]);
            af[2] = __float_as_uint(Ss[r0 + 4]);
            af[3] = __float_as_uint(Ss[r1 + 4]);
            #pragma unroll
            for (int ni = 0; ni < 12; ni++) {
                int col = wnv + ni * 8 + g;
                unsigned b0 = __float_as_uint(Vs[(kk + t) * LDV + col]);
                unsigned b1 = __float_as_uint(Vs[(kk + t + 4) * LDV + col]);
                MMA_TF32(o[ni][0], o[ni][1], o[ni][2], o[ni][3],
                         af[0], af[1], af[2], af[3], b0, b1);
            }
        }
    }

    // ---- finalize: O / l, store ----
    __syncthreads();
    {
        float inv0 = 1.0f / l_s[wm + g];
        float inv1 = 1.0f / l_s[wm + 8 + g];
        float* ob = out + ((size_t)b * NT + q0) * NH;
        #pragma unroll
        for (int ni = 0; ni < 12; ni++) {
            int col = wnv + ni * 8 + t * 2;
            int row0 = wm + g;
            int row1 = wm + 8 + g;
            *(float2*)&ob[(size_t)row0 * NH + col] =
                make_float2(o[ni][0] * inv0, o[ni][1] * inv0);
            *(float2*)&ob[(size_t)row1 * NH + col] =
                make_float2(o[ni][2] * inv1, o[ni][3] * inv1);
        }
    }
}

// ============================================================================
// Launch
// ============================================================================
extern "C" void kernel_launch(void* const* d_in, const int* in_sizes, int n_in,
                              void* d_out, int out_size)
{
    const float* x  = (const float*)d_in[0];
    const float* Wq = (const float*)d_in[1];
    const float* Wk = (const float*)d_in[2];
    const float* Wv = (const float*)d_in[3];
    float* out = (float*)d_out;

    (void)in_sizes; (void)n_in; (void)out_size;

    // QKV projections (full-N 64x192 tile, tf32 mma, LDSM A-fragments)
    dim3 ggrd(M_TOT / GBM, 3);      // (512, 3)
    qkv_mma<<<ggrd, 256>>>(x, Wq, Wk, Wv);

    // Attention (R10 config: 256 threads / 8 warps)
    size_t smem = ATTN_SMEM_FLOATS * sizeof(float);
    cudaFuncSetAttribute(attn_mma, cudaFuncAttributeMaxDynamicSharedMemorySize, (int)smem);
    dim3 agrd(NT / BQ, NB);         // (8, 64)
    attn_mma<<<agrd, 256, smem>>>(out);
}

// round 16
// speedup vs baseline: 2.6602x; 1.7521x over previous
#include <cuda_runtime.h>
#include <cuda_fp16.h>
#include <math.h>

#define NB 64
#define NT 512
#define NC 768
#define NH 192
#define ROT 32
#define M_TOT (NB*NT)

// Scratch for projected q, k, v in fp16 (device globals: no allocation)
__device__ __half g_q[M_TOT * NH];
__device__ __half g_k[M_TOT * NH];
__device__ __half g_v[M_TOT * NH];

// ============================================================================
// helpers
// ============================================================================
__device__ __forceinline__ unsigned h2u(__half2 h) {
    union { __half2 h; unsigned u; } c; c.h = h; return c.u;
}
__device__ __forceinline__ uint2 f4_to_h4(float4 v) {
    uint2 u;
    u.x = h2u(__floats2half2_rn(v.x, v.y));
    u.y = h2u(__floats2half2_rn(v.z, v.w));
    return u;
}
__device__ __forceinline__ float fast_ex2(float x) {
    float y;
    asm("ex2.approx.ftz.f32 %0, %1;" : "=f"(y) : "f"(x));
    return y;
}
#define L2E 1.4426950408889634f

#define LDSM4(r0, r1, r2, r3, addr) \
    asm volatile("ldmatrix.sync.aligned.m8n8.x4.shared.b16 {%0,%1,%2,%3}, [%4];" \
                 : "=r"(r0), "=r"(r1), "=r"(r2), "=r"(r3) : "r"(addr))

#define LDSM4T(r0, r1, r2, r3, addr) \
    asm volatile("ldmatrix.sync.aligned.m8n8.x4.trans.shared.b16 {%0,%1,%2,%3}, [%4];" \
                 : "=r"(r0), "=r"(r1), "=r"(r2), "=r"(r3) : "r"(addr))

#define MMA_F16(c0, c1, c2, c3, a0, a1, a2, a3, b0, b1) \
    asm volatile( \
        "mma.sync.aligned.m16n8k16.row.col.f32.f16.f16.f32 " \
        "{%0,%1,%2,%3}, {%4,%5,%6,%7}, {%8,%9}, {%0,%1,%2,%3};\n" \
        : "+f"(c0), "+f"(c1), "+f"(c2), "+f"(c3) \
        : "r"(a0), "r"(a1), "r"(a2), "r"(a3), "r"(b0), "r"(b1))

// ============================================================================
// QKV projection: out = X(32768,768) @ W(768,192), RoPE fused for q,k.
// fp16 mma.sync.m16n8k16. Block tile 64x192 (full N), BK=32, 256 threads
// (8 warps as 2Mx4N, warp tile 32x48). Double-buffered smem, 1 sync/tile.
// A [m][k] fp16 via ldmatrix.x4; B [k][n] fp16 via ldmatrix.x4.trans.
// ============================================================================
#define GBM 64
#define GBK 32
#define LDAH 40    // A row stride (halves): 80B -> ldmatrix banks 20r mod 32, distinct
#define LDBH 200   // B row stride (halves): 400B -> banks 4r mod 32, distinct
#define ASZH (GBM * LDAH)   // 2560 halves
#define BSZH (GBK * LDBH)   // 6400 halves

__global__ __launch_bounds__(256)
void qkv_mma(const float* __restrict__ X,
             const float* __restrict__ Wq,
             const float* __restrict__ Wk,
             const float* __restrict__ Wv)
{
    __shared__ __half As[2][ASZH];   // [m][k]
    __shared__ __half Bs[2][BSZH];   // [k][n]

    const int which = blockIdx.y;
    const float* W  = (which == 0) ? Wq : (which == 1) ? Wk : Wv;
    __half* outp    = (which == 0) ? g_q : (which == 1) ? g_k : g_v;
    const bool rope = (which < 2);

    const int m0 = blockIdx.x * GBM;

    const int tid  = threadIdx.x;
    const int lane = tid & 31;
    const int wid  = tid >> 5;
    const int wm   = (wid & 1) * 32;    // warp M offset
    const int wn   = (wid >> 1) * 48;   // warp N offset
    const int g    = lane >> 2;
    const int t    = lane & 3;

    // ---- global loader indices ----
    // A: 64x32 tile = 512 float4, 2 per thread
    int am[2], akf[2];
    #pragma unroll
    for (int i = 0; i < 2; i++) {
        int e = tid + i * 256;
        am[i]  = e >> 3;            // 0..63
        akf[i] = (e & 7) * 4;       // 0,4,...,28
    }
    // B: 32x192 tile = 1536 float4, 6 per thread
    int brow[6], bcol[6];
    #pragma unroll
    for (int j = 0; j < 6; j++) {
        int e = tid + j * 256;      // 0..1535
        brow[j] = e / 48;           // 0..31
        bcol[j] = (e - brow[j] * 48) * 4;
    }

    // ---- ldmatrix base addresses ----
    const unsigned sA = (unsigned)__cvta_generic_to_shared(&As[0][0]);
    const unsigned sB = (unsigned)__cvta_generic_to_shared(&Bs[0][0]);
    unsigned a_addr[2];
    #pragma unroll
    for (int mi = 0; mi < 2; mi++) {
        int row = wm + mi * 16 + (lane & 7) + ((lane >> 3) & 1) * 8;
        int kof = ((lane >> 4) & 1) * 8;
        a_addr[mi] = sA + (unsigned)(row * LDAH + kof) * 2u;
    }
    unsigned b_addr[3];
    #pragma unroll
    for (int j = 0; j < 3; j++) {
        int krow = lane & 15;
        int ncol = wn + j * 16 + ((lane >> 4) & 1) * 8;
        b_addr[j] = sB + (unsigned)(krow * LDBH + ncol) * 2u;
    }

    float4 ra[2], rb[6];

    float c[2][6][4];
    #pragma unroll
    for (int mi = 0; mi < 2; mi++)
        #pragma unroll
        for (int ni = 0; ni < 6; ni++)
            #pragma unroll
            for (int r = 0; r < 4; r++) c[mi][ni][r] = 0.f;

    const int K_TILES = NC / GBK;   // 24

    // ---- prologue: tile 0 ----
    #pragma unroll
    for (int i = 0; i < 2; i++)
        ra[i] = *(const float4*)(X + (size_t)(m0 + am[i]) * NC + akf[i]);
    #pragma unroll
    for (int j = 0; j < 6; j++)
        rb[j] = *(const float4*)(W + (size_t)brow[j] * NH + bcol[j]);
    #pragma unroll
    for (int i = 0; i < 2; i++)
        *(uint2*)&As[0][am[i] * LDAH + akf[i]] = f4_to_h4(ra[i]);
    #pragma unroll
    for (int j = 0; j < 6; j++)
        *(uint2*)&Bs[0][brow[j] * LDBH + bcol[j]] = f4_to_h4(rb[j]);
    __syncthreads();

    for (int kt = 0; kt < K_TILES; kt++) {
        const int cur = kt & 1;
        const bool more = (kt + 1 < K_TILES);
        if (more) {
            int k0 = (kt + 1) * GBK;
            #pragma unroll
            for (int i = 0; i < 2; i++)
                ra[i] = *(const float4*)(X + (size_t)(m0 + am[i]) * NC + k0 + akf[i]);
            #pragma unroll
            for (int j = 0; j < 6; j++)
                rb[j] = *(const float4*)(W + (size_t)(k0 + brow[j]) * NH + bcol[j]);
        }

        const unsigned abuf = cur ? (unsigned)(ASZH * 2) : 0u;
        const unsigned bbuf = cur ? (unsigned)(BSZH * 2) : 0u;

        #pragma unroll
        for (int ks = 0; ks < GBK; ks += 16) {
            unsigned af[2][4];
            unsigned bf[6][2];
            #pragma unroll
            for (int mi = 0; mi < 2; mi++)
                LDSM4(af[mi][0], af[mi][1], af[mi][2], af[mi][3],
                      a_addr[mi] + abuf + (unsigned)ks * 2u);
            #pragma unroll
            for (int j = 0; j < 3; j++)
                LDSM4T(bf[2*j][0], bf[2*j][1], bf[2*j+1][0], bf[2*j+1][1],
                       b_addr[j] + bbuf + (unsigned)(ks * LDBH) * 2u);
            #pragma unroll
            for (int mi = 0; mi < 2; mi++)
                #pragma unroll
                for (int ni = 0; ni < 6; ni++)
                    MMA_F16(c[mi][ni][0], c[mi][ni][1], c[mi][ni][2], c[mi][ni][3],
                            af[mi][0], af[mi][1], af[mi][2], af[mi][3],
                            bf[ni][0], bf[ni][1]);
        }

        if (more) {
            const int nxt = cur ^ 1;
            #pragma unroll
            for (int i = 0; i < 2; i++)
                *(uint2*)&As[nxt][am[i] * LDAH + akf[i]] = f4_to_h4(ra[i]);
            #pragma unroll
            for (int j = 0; j < 6; j++)
                *(uint2*)&Bs[nxt][brow[j] * LDBH + bcol[j]] = f4_to_h4(rb[j]);
            __syncthreads();
        }
    }

    // ---- epilogue: RoPE on cols < 32 (q,k only), store half2 pairs ----
    const float LOG2_THETA = 13.287712379549449f;

    #pragma unroll
    for (int mi = 0; mi < 2; mi++) {
        #pragma unroll
        for (int ni = 0; ni < 6; ni++) {
            int col = wn + ni * 8 + t * 2;
            #pragma unroll
            for (int half = 0; half < 2; half++) {
                int row = m0 + wm + mi * 16 + g + half * 8;
                float x1 = c[mi][ni][half * 2 + 0];
                float x2 = c[mi][ni][half * 2 + 1];
                if (rope && col < ROT) {
                    int jh = col >> 1;
                    int tpos = row & (NT - 1);
                    float inv = exp2f(-(float)(2 * jh) * (1.0f / 32.0f) * LOG2_THETA);
                    float ang = (float)tpos * inv;
                    float sn, cs;
                    sincosf(ang, &sn, &cs);
                    float r1 = x1 * cs - x2 * sn;
                    float r2 = x2 * cs + x1 * sn;
                    x1 = r1; x2 = r2;
                }
                *(__half2*)&outp[(size_t)row * NH + col] = __floats2half2_rn(x1, x2);
            }
        }
    }
}

// ============================================================================
// Tensor-core flash attention, fp16 mma (m16n8k16), fp32 softmax/accum.
// Block = (batch b, query tile of 64 rows). 256 threads = 8 warps.
// S: warps 4Mx2N (16x32 each). PV: warps 4Mx2N (16x96 each).
// ============================================================================
#define BQ  64
#define BKT 64
#define LDQH 200   // Q/K/V smem row stride (halves): 400B -> banks 4r, distinct
#define LDS  68    // S scores stride (floats)
#define LDPH 72    // P stride (halves): 144B -> banks 36r mod 32 = 4r, distinct

#define Q_BYTES  (BQ * LDQH * 2)
#define S_BYTES  (BQ * LDS * 4)
#define P_BYTES  (BQ * LDPH * 2)
#define ATTN_SMEM_BYTES (3 * Q_BYTES + S_BYTES + P_BYTES + 3 * BQ * 4)

__global__ __launch_bounds__(256)
void attn_mma(float* __restrict__ out)
{
    extern __shared__ char smb[];
    __half* Qs = (__half*)smb;                       // [64][LDQH]
    __half* Ks = (__half*)(smb + Q_BYTES);           // [64][LDQH]
    __half* Vs = (__half*)(smb + 2 * Q_BYTES);       // [64][LDQH]
    float*  Ss = (float*)(smb + 3 * Q_BYTES);        // [64][LDS]
    __half* Ps = (__half*)(smb + 3 * Q_BYTES + S_BYTES);  // [64][LDPH]
    float*  m_s = (float*)(smb + 3 * Q_BYTES + S_BYTES + P_BYTES);
    float*  l_s = m_s + BQ;
    float*  c_s = l_s + BQ;

    const int b   = blockIdx.y;
    const int qt  = gridDim.x - 1 - blockIdx.x;   // heavy tiles first
    const int q0  = qt * BQ;
    const int tid = threadIdx.x;
    const int lane = tid & 31;
    const int wid  = tid >> 5;
    const int g    = lane >> 2;       // 0..7
    const int t    = lane & 3;        // 0..3
    const int wm   = (wid & 3) * 16;  // warp M offset (rows)
    const int wns  = (wid >> 2) * 32; // warp N offset for S
    const int wnv  = (wid >> 2) * 96; // warp N offset for PV / O

    const unsigned sQ = (unsigned)__cvta_generic_to_shared(Qs);
    const unsigned sK = (unsigned)__cvta_generic_to_shared(Ks);
    const unsigned sV = (unsigned)__cvta_generic_to_shared(Vs);
    const unsigned sP = (unsigned)__cvta_generic_to_shared(Ps);

    // ldmatrix lane bases
    const int arow = (lane & 7) + ((lane >> 3) & 1) * 8;   // fragment row within 16
    const int akof = ((lane >> 4) & 1) * 8;                // k-offset for A tiles
    const unsigned qa_base = sQ + (unsigned)((wm + arow) * LDQH + akof) * 2u;
    const unsigned pa_base = sP + (unsigned)((wm + arow) * LDPH + akof) * 2u;

    unsigned ka_base[2];   // K non-trans: rows = keys
    #pragma unroll
    for (int j = 0; j < 2; j++) {
        int nrow = wns + j * 16 + (lane & 7) + ((lane >> 4) & 1) * 8;
        int kof  = ((lane >> 3) & 1) * 8;
        ka_base[j] = sK + (unsigned)(nrow * LDQH + kof) * 2u;
    }
    unsigned va_base[6];   // V trans: rows = keys, cols = h
    #pragma unroll
    for (int j = 0; j < 6; j++) {
        int krow = lane & 15;
        int ncol = wnv + j * 16 + ((lane >> 4) & 1) * 8;
        va_base[j] = sV + (unsigned)(krow * LDQH + ncol) * 2u;
    }

    // ---- load Q tile: 1536 uint4 / 256 threads = 6 each ----
    {
        const uint4* src = (const uint4*)(g_q + ((size_t)b * NT + q0) * NH);
        #pragma unroll
        for (int i = 0; i < 6; i++) {
            int e = tid + i * 256;          // 0..1535
            int row = e / 24, c8 = e - row * 24;
            *(uint4*)&Qs[row * LDQH + c8 * 8] = src[e];
        }
    }
    if (tid < BQ) { m_s[tid] = -INFINITY; l_s[tid] = 0.f; }

    float o[12][4];
    #pragma unroll
    for (int ni = 0; ni < 12; ni++)
        #pragma unroll
        for (int r = 0; r < 4; r++) o[ni][r] = 0.f;

    const float scale = 1.0f / sqrtf((float)NH);

    for (int kt = 0; kt <= qt; kt++) {
        __syncthreads();   // prev PV done before K/V/S overwrite

        // ---- load K, V tiles (fp16 direct copy) ----
        {
            const uint4* ksrc = (const uint4*)(g_k + ((size_t)b * NT + kt * BKT) * NH);
            const uint4* vsrc = (const uint4*)(g_v + ((size_t)b * NT + kt * BKT) * NH);
            #pragma unroll
            for (int i = 0; i < 6; i++) {
                int e = tid + i * 256;
                int row = e / 24, c8 = e - row * 24;
                *(uint4*)&Ks[row * LDQH + c8 * 8] = ksrc[e];
                *(uint4*)&Vs[row * LDQH + c8 * 8] = vsrc[e];
            }
        }
        __syncthreads();

        // ---- S = Q K^T via fp16 mma (each warp: 16 rows x 32 cols) ----
        float s[4][4];
        #pragma unroll
        for (int ni = 0; ni < 4; ni++)
            #pragma unroll
            for (int r = 0; r < 4; r++) s[ni][r] = 0.f;

        #pragma unroll 3
        for (int ks = 0; ks < NH; ks += 16) {
            unsigned af[4];
            LDSM4(af[0], af[1], af[2], af[3], qa_base + (unsigned)ks * 2u);
            unsigned bf[4][2];
            #pragma unroll
            for (int j = 0; j < 2; j++)
                LDSM4(bf[2*j][0], bf[2*j][1], bf[2*j+1][0], bf[2*j+1][1],
                      ka_base[j] + (unsigned)ks * 2u);
            #pragma unroll
            for (int ni = 0; ni < 4; ni++)
                MMA_F16(s[ni][0], s[ni][1], s[ni][2], s[ni][3],
                        af[0], af[1], af[2], af[3],
                        bf[ni][0], bf[ni][1]);
        }

        // ---- scale + causal mask, write S (f32) to smem ----
        const bool diag = (kt == qt);
        #pragma unroll
        for (int ni = 0; ni < 4; ni++) {
            #pragma unroll
            for (int half = 0; half < 2; half++) {
                int row = wm + half * 8 + g;
                #pragma unroll
                for (int j = 0; j < 2; j++) {
                    int col = wns + ni * 8 + t * 2 + j;
                    float v = s[ni][half * 2 + j] * scale;
                    if (diag && col > row) v = -INFINITY;
                    Ss[row * LDS + col] = v;
                }
            }
        }
        __syncthreads();

        // ---- online softmax: 4 threads per row, 16 cols each; P -> fp16 ----
        {
            int r   = tid >> 2;
            int sub = tid & 3;
            float* rp = Ss + r * LDS + sub * 16;

            float p[16];
            *(float4*)(p + 0)  = *(float4*)(rp + 0);
            *(float4*)(p + 4)  = *(float4*)(rp + 4);
            *(float4*)(p + 8)  = *(float4*)(rp + 8);
            *(float4*)(p + 12) = *(float4*)(rp + 12);

            float tmax = p[0];
            #pragma unroll
            for (int i = 1; i < 16; i++) tmax = fmaxf(tmax, p[i]);
            tmax = fmaxf(tmax, __shfl_xor_sync(0xffffffffu, tmax, 1));
            tmax = fmaxf(tmax, __shfl_xor_sync(0xffffffffu, tmax, 2));

            float mo   = m_s[r];
            float rmax = fmaxf(mo, tmax);
            float corr = fast_ex2((mo - rmax) * L2E);

            float sum = 0.f;
            #pragma unroll
            for (int i = 0; i < 16; i++) {
                p[i] = fast_ex2((p[i] - rmax) * L2E);
                sum += p[i];
            }
            __half* pp = Ps + r * LDPH + sub * 16;
            #pragma unroll
            for (int i = 0; i < 8; i++)
                *(__half2*)(pp + 2 * i) = __floats2half2_rn(p[2*i], p[2*i+1]);

            sum += __shfl_xor_sync(0xffffffffu, sum, 1);
            sum += __shfl_xor_sync(0xffffffffu, sum, 2);
            if (sub == 0) {
                l_s[r] = l_s[r] * corr + sum;
                m_s[r] = rmax;
                c_s[r] = corr;
            }
        }
        __syncthreads();

        // ---- O = O*corr + P V via fp16 mma (each warp: 16 rows x 96 cols) ----
        {
            float corr0 = c_s[wm + g];
            float corr1 = c_s[wm + 8 + g];
            #pragma unroll
            for (int ni = 0; ni < 12; ni++) {
                o[ni][0] *= corr0; o[ni][1] *= corr0;
                o[ni][2] *= corr1; o[ni][3] *= corr1;
            }
        }
        #pragma unroll
        for (int kk = 0; kk < BKT; kk += 16) {
            unsigned af[4];
            LDSM4(af[0], af[1], af[2], af[3], pa_base + (unsigned)kk * 2u);
            #pragma unroll
            for (int j = 0; j < 6; j++) {
                unsigned b0a, b0b, b1a, b1b;
                LDSM4T(b0a, b0b, b1a, b1b,
                       va_base[j] + (unsigned)(kk * LDQH) * 2u);
                MMA_F16(o[2*j][0], o[2*j][1], o[2*j][2], o[2*j][3],
                        af[0], af[1], af[2], af[3], b0a, b0b);
                MMA_F16(o[2*j+1][0], o[2*j+1][1], o[2*j+1][2], o[2*j+1][3],
                        af[0], af[1], af[2], af[3], b1a, b1b);
            }
        }
    }

    // ---- finalize: O / l, store ----
    __syncthreads();
    {
        float inv0 = 1.0f / l_s[wm + g];
        float inv1 = 1.0f / l_s[wm + 8 + g];
        float* ob = out + ((size_t)b * NT + q0) * NH;
        #pragma unroll
        for (int ni = 0; ni < 12; ni++) {
            int col = wnv + ni * 8 + t * 2;
            int row0 = wm + g;
            int row1 = wm + 8 + g;
            *(float2*)&ob[(size_t)row0 * NH + col] =
                make_float2(o[ni][0] * inv0, o[ni][1] * inv0);
            *(float2*)&ob[(size_t)row1 * NH + col] =
                make_float2(o[ni][2] * inv1, o[ni][3] * inv1);
        }
    }
}

// ============================================================================
// Launch
// ============================================================================
extern "C" void kernel_launch(void* const* d_in, const int* in_sizes, int n_in,
                              void* d_out, int out_size)
{
    const float* x  = (const float*)d_in[0];
    const float* Wq = (const float*)d_in[1];
    const float* Wk = (const float*)d_in[2];
    const float* Wv = (const float*)d_in[3];
    float* out = (float*)d_out;

    (void)in_sizes; (void)n_in; (void)out_size;

    // QKV projections (fp16 mma, full-N 64x192 tile)
    dim3 ggrd(M_TOT / GBM, 3);      // (512, 3)
    qkv_mma<<<ggrd, 256>>>(x, Wq, Wk, Wv);

    // Attention (fp16 mma, 104 KB smem -> up to 2 blocks/SM)
    cudaFuncSetAttribute(attn_mma, cudaFuncAttributeMaxDynamicSharedMemorySize,
                         ATTN_SMEM_BYTES);
    dim3 agrd(NT / BQ, NB);         // (8, 64)
    attn_mma<<<agrd, 256, ATTN_SMEM_BYTES>>>(out);
}

// round 17
// speedup vs baseline: 2.9676x; 1.1156x over previous
#include <cuda_runtime.h>
#include <cuda_fp16.h>
#include <math.h>

#define NB 64
#define NT 512
#define NC 768
#define NH 192
#define ROT 32
#define M_TOT (NB*NT)

// Device-global scratch (no allocation at launch time)
__device__ __half g_q[M_TOT * NH];
__device__ __half g_k[M_TOT * NH];
__device__ __half g_v[M_TOT * NH];
__device__ __half g_xh[(size_t)M_TOT * NC];   // fp16 copy of X
__device__ __half g_wh[3 * NC * NH];          // fp16 copies of Wq,Wk,Wv

// ============================================================================
// helpers
// ============================================================================
__device__ __forceinline__ unsigned h2u(__half2 h) {
    union { __half2 h; unsigned u; } c; c.h = h; return c.u;
}
__device__ __forceinline__ uint2 f4_to_h4(float4 v) {
    uint2 u;
    u.x = h2u(__floats2half2_rn(v.x, v.y));
    u.y = h2u(__floats2half2_rn(v.z, v.w));
    return u;
}
__device__ __forceinline__ float fast_ex2(float x) {
    float y;
    asm("ex2.approx.ftz.f32 %0, %1;" : "=f"(y) : "f"(x));
    return y;
}
#define L2E 1.4426950408889634f

#define LDSM4(r0, r1, r2, r3, addr) \
    asm volatile("ldmatrix.sync.aligned.m8n8.x4.shared.b16 {%0,%1,%2,%3}, [%4];" \
                 : "=r"(r0), "=r"(r1), "=r"(r2), "=r"(r3) : "r"(addr))

#define LDSM4T(r0, r1, r2, r3, addr) \
    asm volatile("ldmatrix.sync.aligned.m8n8.x4.trans.shared.b16 {%0,%1,%2,%3}, [%4];" \
                 : "=r"(r0), "=r"(r1), "=r"(r2), "=r"(r3) : "r"(addr))

#define MMA_F16(c0, c1, c2, c3, a0, a1, a2, a3, b0, b1) \
    asm volatile( \
        "mma.sync.aligned.m16n8k16.row.col.f32.f16.f16.f32 " \
        "{%0,%1,%2,%3}, {%4,%5,%6,%7}, {%8,%9}, {%0,%1,%2,%3};\n" \
        : "+f"(c0), "+f"(c1), "+f"(c2), "+f"(c3) \
        : "r"(a0), "r"(a1), "r"(a2), "r"(a3), "r"(b0), "r"(b1))

#define CP16(dst, src) \
    asm volatile("cp.async.cg.shared.global [%0], [%1], 16;" \
                 :: "r"(dst), "l"(src))
#define CP_COMMIT() asm volatile("cp.async.commit_group;")
#define CP_WAIT2()  asm volatile("cp.async.wait_group 2;" ::: "memory")

// ============================================================================
// fp32 -> fp16 conversion prepasses
// ============================================================================
__global__ __launch_bounds__(256)
void convert_x(const float* __restrict__ X)
{
    size_t i = ((size_t)blockIdx.x * 256 + threadIdx.x) * 8;
    float4 a = *(const float4*)(X + i);
    float4 b = *(const float4*)(X + i + 4);
    uint2 h0 = f4_to_h4(a), h1 = f4_to_h4(b);
    *(uint4*)&g_xh[i] = make_uint4(h0.x, h0.y, h1.x, h1.y);
}

__global__ __launch_bounds__(256)
void convert_w(const float* __restrict__ Wq,
               const float* __restrict__ Wk,
               const float* __restrict__ Wv)
{
    int i = (blockIdx.x * 256 + threadIdx.x) * 8;   // 0 .. 3*NC*NH-8
    int which = i / (NC * NH);
    int off   = i - which * (NC * NH);
    const float* W = (which == 0) ? Wq : (which == 1) ? Wk : Wv;
    float4 a = *(const float4*)(W + off);
    float4 b = *(const float4*)(W + off + 4);
    uint2 h0 = f4_to_h4(a), h1 = f4_to_h4(b);
    *(uint4*)&g_wh[i] = make_uint4(h0.x, h0.y, h1.x, h1.y);
}

// ============================================================================
// QKV projection: out = Xh(32768,768) @ Wh(768,192), RoPE fused for q,k.
// fp16 mma.sync.m16n8k16, 4-stage cp.async pipeline, 1 sync per k-tile.
// Block tile 64x192 (full N), BK=32, 256 threads (8 warps 2Mx4N, warp 32x48).
// ============================================================================
#define GBM 64
#define GBK 32
#define LDAH 40    // A row stride (halves): 80B -> ldmatrix banks 20r mod 32, distinct
#define LDBH 200   // B row stride (halves): 400B -> banks 4r mod 32, distinct
#define ASZH (GBM * LDAH)   // 2560 halves
#define BSZH (GBK * LDBH)   // 6400 halves
#define STGH (ASZH + BSZH)  // 8960 halves per stage
#define QKV_SMEM_BYTES (4 * STGH * 2)   // 71680 B

__global__ __launch_bounds__(256, 2)
void qkv_mma()
{
    extern __shared__ __half qsm[];

    const int which = blockIdx.y;
    const __half* Xh = g_xh;
    const __half* Wh = g_wh + which * (NC * NH);
    __half* outp     = (which == 0) ? g_q : (which == 1) ? g_k : g_v;
    const bool rope  = (which < 2);

    const int m0 = blockIdx.x * GBM;

    const int tid  = threadIdx.x;
    const int lane = tid & 31;
    const int wid  = tid >> 5;
    const int wm   = (wid & 1) * 32;    // warp M offset
    const int wn   = (wid >> 1) * 48;   // warp N offset
    const int g    = lane >> 2;
    const int t    = lane & 3;

    // ---- cp.async chunk indices ----
    // A: 64 rows x 32 halves = 256 x 16B chunks, 1/thread
    const int arow = tid >> 2;          // 0..63
    const int achk = (tid & 3) * 8;     // halves offset: 0,8,16,24
    // B: 32 rows x 192 halves = 768 x 16B chunks, 3/thread
    int brow[3], bchk[3];
    #pragma unroll
    for (int j = 0; j < 3; j++) {
        int e = tid + j * 256;          // 0..767
        brow[j] = e / 24;               // 0..31
        bchk[j] = (e - brow[j] * 24) * 8;
    }

    const unsigned sBase = (unsigned)__cvta_generic_to_shared(qsm);
    const unsigned dstA  = sBase + (unsigned)(arow * LDAH + achk) * 2u;
    unsigned dstB[3];
    #pragma unroll
    for (int j = 0; j < 3; j++)
        dstB[j] = sBase + (unsigned)(ASZH + brow[j] * LDBH + bchk[j]) * 2u;

    // ---- ldmatrix base addresses (stage 0) ----
    unsigned a_addr[2];
    #pragma unroll
    for (int mi = 0; mi < 2; mi++) {
        int row = wm + mi * 16 + (lane & 7) + ((lane >> 3) & 1) * 8;
        int kof = ((lane >> 4) & 1) * 8;
        a_addr[mi] = sBase + (unsigned)(row * LDAH + kof) * 2u;
    }
    unsigned b_addr[3];
    #pragma unroll
    for (int j = 0; j < 3; j++) {
        int krow = lane & 15;
        int ncol = wn + j * 16 + ((lane >> 4) & 1) * 8;
        b_addr[j] = sBase + (unsigned)(ASZH + krow * LDBH + ncol) * 2u;
    }

    float c[2][6][4];
    #pragma unroll
    for (int mi = 0; mi < 2; mi++)
        #pragma unroll
        for (int ni = 0; ni < 6; ni++)
            #pragma unroll
            for (int r = 0; r < 4; r++) c[mi][ni][r] = 0.f;

    const int K_TILES = NC / GBK;   // 24

    // ---- prologue: issue tiles 0,1,2 into stages 0,1,2 ----
    #pragma unroll
    for (int s = 0; s < 3; s++) {
        int k0 = s * GBK;
        unsigned stg = (unsigned)(s * STGH * 2);
        CP16(dstA + stg, Xh + (size_t)(m0 + arow) * NC + k0 + achk);
        #pragma unroll
        for (int j = 0; j < 3; j++)
            CP16(dstB[j] + stg, Wh + (size_t)(k0 + brow[j]) * NH + bchk[j]);
        CP_COMMIT();
    }

    for (int kt = 0; kt < K_TILES; kt++) {
        CP_WAIT2();            // tile kt resident
        __syncthreads();       // all warps done with stage (kt-1)%4, tile kt visible

        // issue tile kt+3 into stage (kt+3)%4  (== (kt-1)%4, freed by sync above)
        if (kt + 3 < K_TILES) {
            int k0 = (kt + 3) * GBK;
            unsigned stg = (unsigned)(((kt + 3) & 3) * STGH * 2);
            CP16(dstA + stg, Xh + (size_t)(m0 + arow) * NC + k0 + achk);
            #pragma unroll
            for (int j = 0; j < 3; j++)
                CP16(dstB[j] + stg, Wh + (size_t)(k0 + brow[j]) * NH + bchk[j]);
        }
        CP_COMMIT();           // commit every iteration to keep group indexing aligned

        const unsigned stg = (unsigned)((kt & 3) * STGH * 2);
        #pragma unroll
        for (int ks = 0; ks < GBK; ks += 16) {
            unsigned af[2][4];
            unsigned bf[6][2];
            #pragma unroll
            for (int mi = 0; mi < 2; mi++)
                LDSM4(af[mi][0], af[mi][1], af[mi][2], af[mi][3],
                      a_addr[mi] + stg + (unsigned)ks * 2u);
            #pragma unroll
            for (int j = 0; j < 3; j++)
                LDSM4T(bf[2*j][0], bf[2*j][1], bf[2*j+1][0], bf[2*j+1][1],
                       b_addr[j] + stg + (unsigned)(ks * LDBH) * 2u);
            #pragma unroll
            for (int mi = 0; mi < 2; mi++)
                #pragma unroll
                for (int ni = 0; ni < 6; ni++)
                    MMA_F16(c[mi][ni][0], c[mi][ni][1], c[mi][ni][2], c[mi][ni][3],
                            af[mi][0], af[mi][1], af[mi][2], af[mi][3],
                            bf[ni][0], bf[ni][1]);
        }
    }

    // ---- epilogue: RoPE on cols < 32 (q,k only), store half2 pairs ----
    const float LOG2_THETA = 13.287712379549449f;

    #pragma unroll
    for (int mi = 0; mi < 2; mi++) {
        #pragma unroll
        for (int ni = 0; ni < 6; ni++) {
            int col = wn + ni * 8 + t * 2;
            #pragma unroll
            for (int half = 0; half < 2; half++) {
                int row = m0 + wm + mi * 16 + g + half * 8;
                float x1 = c[mi][ni][half * 2 + 0];
                float x2 = c[mi][ni][half * 2 + 1];
                if (rope && col < ROT) {
                    int jh = col >> 1;
                    int tpos = row & (NT - 1);
                    float inv = exp2f(-(float)(2 * jh) * (1.0f / 32.0f) * LOG2_THETA);
                    float ang = (float)tpos * inv;
                    float sn, cs;
                    sincosf(ang, &sn, &cs);
                    float r1 = x1 * cs - x2 * sn;
                    float r2 = x2 * cs + x1 * sn;
                    x1 = r1; x2 = r2;
                }
                *(__half2*)&outp[(size_t)row * NH + col] = __floats2half2_rn(x1, x2);
            }
        }
    }
}

// ============================================================================
// Tensor-core flash attention, fp16 mma (m16n8k16), fp32 softmax/accum.
// Block = (batch b, query tile of 64 rows). 256 threads = 8 warps.
// (Unchanged from R13-15 winner.)
// ============================================================================
#define BQ  64
#define BKT 64
#define LDQH 200   // Q/K/V smem row stride (halves): 400B -> banks 4r, distinct
#define LDS  68    // S scores stride (floats)
#define LDPH 72    // P stride (halves): 144B -> banks 4r mod 32, distinct

#define Q_BYTES  (BQ * LDQH * 2)
#define S_BYTES  (BQ * LDS * 4)
#define P_BYTES  (BQ * LDPH * 2)
#define ATTN_SMEM_BYTES (3 * Q_BYTES + S_BYTES + P_BYTES + 3 * BQ * 4)

__global__ __launch_bounds__(256)
void attn_mma(float* __restrict__ out)
{
    extern __shared__ char smb[];
    __half* Qs = (__half*)smb;                       // [64][LDQH]
    __half* Ks = (__half*)(smb + Q_BYTES);           // [64][LDQH]
    __half* Vs = (__half*)(smb + 2 * Q_BYTES);       // [64][LDQH]
    float*  Ss = (float*)(smb + 3 * Q_BYTES);        // [64][LDS]
    __half* Ps = (__half*)(smb + 3 * Q_BYTES + S_BYTES);  // [64][LDPH]
    float*  m_s = (float*)(smb + 3 * Q_BYTES + S_BYTES + P_BYTES);
    float*  l_s = m_s + BQ;
    float*  c_s = l_s + BQ;

    const int b   = blockIdx.y;
    const int qt  = gridDim.x - 1 - blockIdx.x;   // heavy tiles first
    const int q0  = qt * BQ;
    const int tid = threadIdx.x;
    const int lane = tid & 31;
    const int wid  = tid >> 5;
    const int g    = lane >> 2;       // 0..7
    const int t    = lane & 3;        // 0..3
    const int wm   = (wid & 3) * 16;  // warp M offset (rows)
    const int wns  = (wid >> 2) * 32; // warp N offset for S
    const int wnv  = (wid >> 2) * 96; // warp N offset for PV / O

    const unsigned sQ = (unsigned)__cvta_generic_to_shared(Qs);
    const unsigned sK = (unsigned)__cvta_generic_to_shared(Ks);
    const unsigned sV = (unsigned)__cvta_generic_to_shared(Vs);
    const unsigned sP = (unsigned)__cvta_generic_to_shared(Ps);

    // ldmatrix lane bases
    const int arow = (lane & 7) + ((lane >> 3) & 1) * 8;
    const int akof = ((lane >> 4) & 1) * 8;
    const unsigned qa_base = sQ + (unsigned)((wm + arow) * LDQH + akof) * 2u;
    const unsigned pa_base = sP + (unsigned)((wm + arow) * LDPH + akof) * 2u;

    unsigned ka_base[2];   // K non-trans: rows = keys
    #pragma unroll
    for (int j = 0; j < 2; j++) {
        int nrow = wns + j * 16 + (lane & 7) + ((lane >> 4) & 1) * 8;
        int kof  = ((lane >> 3) & 1) * 8;
        ka_base[j] = sK + (unsigned)(nrow * LDQH + kof) * 2u;
    }
    unsigned va_base[6];   // V trans: rows = keys, cols = h
    #pragma unroll
    for (int j = 0; j < 6; j++) {
        int krow = lane & 15;
        int ncol = wnv + j * 16 + ((lane >> 4) & 1) * 8;
        va_base[j] = sV + (unsigned)(krow * LDQH + ncol) * 2u;
    }

    // ---- load Q tile: 1536 uint4 / 256 threads = 6 each ----
    {
        const uint4* src = (const uint4*)(g_q + ((size_t)b * NT + q0) * NH);
        #pragma unroll
        for (int i = 0; i < 6; i++) {
            int e = tid + i * 256;          // 0..1535
            int row = e / 24, c8 = e - row * 24;
            *(uint4*)&Qs[row * LDQH + c8 * 8] = src[e];
        }
    }
    if (tid < BQ) { m_s[tid] = -INFINITY; l_s[tid] = 0.f; }

    float o[12][4];
    #pragma unroll
    for (int ni = 0; ni < 12; ni++)
        #pragma unroll
        for (int r = 0; r < 4; r++) o[ni][r] = 0.f;

    const float scale = 1.0f / sqrtf((float)NH);

    for (int kt = 0; kt <= qt; kt++) {
        __syncthreads();   // prev PV done before K/V/S overwrite

        // ---- load K, V tiles (fp16 direct copy) ----
        {
            const uint4* ksrc = (const uint4*)(g_k + ((size_t)b * NT + kt * BKT) * NH);
            const uint4* vsrc = (const uint4*)(g_v + ((size_t)b * NT + kt * BKT) * NH);
            #pragma unroll
            for (int i = 0; i < 6; i++) {
                int e = tid + i * 256;
                int row = e / 24, c8 = e - row * 24;
                *(uint4*)&Ks[row * LDQH + c8 * 8] = ksrc[e];
                *(uint4*)&Vs[row * LDQH + c8 * 8] = vsrc[e];
            }
        }
        __syncthreads();

        // ---- S = Q K^T via fp16 mma (each warp: 16 rows x 32 cols) ----
        float s[4][4];
        #pragma unroll
        for (int ni = 0; ni < 4; ni++)
            #pragma unroll
            for (int r = 0; r < 4; r++) s[ni][r] = 0.f;

        #pragma unroll 3
        for (int ks = 0; ks < NH; ks += 16) {
            unsigned af[4];
            LDSM4(af[0], af[1], af[2], af[3], qa_base + (unsigned)ks * 2u);
            unsigned bf[4][2];
            #pragma unroll
            for (int j = 0; j < 2; j++)
                LDSM4(bf[2*j][0], bf[2*j][1], bf[2*j+1][0], bf[2*j+1][1],
                      ka_base[j] + (unsigned)ks * 2u);
            #pragma unroll
            for (int ni = 0; ni < 4; ni++)
                MMA_F16(s[ni][0], s[ni][1], s[ni][2], s[ni][3],
                        af[0], af[1], af[2], af[3],
                        bf[ni][0], bf[ni][1]);
        }

        // ---- scale + causal mask, write S (f32) to smem ----
        const bool diag = (kt == qt);
        #pragma unroll
        for (int ni = 0; ni < 4; ni++) {
            #pragma unroll
            for (int half = 0; half < 2; half++) {
                int row = wm + half * 8 + g;
                #pragma unroll
                for (int j = 0; j < 2; j++) {
                    int col = wns + ni * 8 + t * 2 + j;
                    float v = s[ni][half * 2 + j] * scale;
                    if (diag && col > row) v = -INFINITY;
                    Ss[row * LDS + col] = v;
                }
            }
        }
        __syncthreads();

        // ---- online softmax: 4 threads per row, 16 cols each; P -> fp16 ----
        {
            int r   = tid >> 2;
            int sub = tid & 3;
            float* rp = Ss + r * LDS + sub * 16;

            float p[16];
            *(float4*)(p + 0)  = *(float4*)(rp + 0);
            *(float4*)(p + 4)  = *(float4*)(rp + 4);
            *(float4*)(p + 8)  = *(float4*)(rp + 8);
            *(float4*)(p + 12) = *(float4*)(rp + 12);

            float tmax = p[0];
            #pragma unroll
            for (int i = 1; i < 16; i++) tmax = fmaxf(tmax, p[i]);
            tmax = fmaxf(tmax, __shfl_xor_sync(0xffffffffu, tmax, 1));
            tmax = fmaxf(tmax, __shfl_xor_sync(0xffffffffu, tmax, 2));

            float mo   = m_s[r];
            float rmax = fmaxf(mo, tmax);
            float corr = fast_ex2((mo - rmax) * L2E);

            float sum = 0.f;
            #pragma unroll
            for (int i = 0; i < 16; i++) {
                p[i] = fast_ex2((p[i] - rmax) * L2E);
                sum += p[i];
            }
            __half* pp = Ps + r * LDPH + sub * 16;
            #pragma unroll
            for (int i = 0; i < 8; i++)
                *(__half2*)(pp + 2 * i) = __floats2half2_rn(p[2*i], p[2*i+1]);

            sum += __shfl_xor_sync(0xffffffffu, sum, 1);
            sum += __shfl_xor_sync(0xffffffffu, sum, 2);
            if (sub == 0) {
                l_s[r] = l_s[r] * corr + sum;
                m_s[r] = rmax;
                c_s[r] = corr;
            }
        }
        __syncthreads();

        // ---- O = O*corr + P V via fp16 mma (each warp: 16 rows x 96 cols) ----
        {
            float corr0 = c_s[wm + g];
            float corr1 = c_s[wm + 8 + g];
            #pragma unroll
            for (int ni = 0; ni < 12; ni++) {
                o[ni][0] *= corr0; o[ni][1] *= corr0;
                o[ni][2] *= corr1; o[ni][3] *= corr1;
            }
        }
        #pragma unroll
        for (int kk = 0; kk < BKT; kk += 16) {
            unsigned af[4];
            LDSM4(af[0], af[1], af[2], af[3], pa_base + (unsigned)kk * 2u);
            #pragma unroll
            for (int j = 0; j < 6; j++) {
                unsigned b0a, b0b, b1a, b1b;
                LDSM4T(b0a, b0b, b1a, b1b,
                       va_base[j] + (unsigned)(kk * LDQH) * 2u);
                MMA_F16(o[2*j][0], o[2*j][1], o[2*j][2], o[2*j][3],
                        af[0], af[1], af[2], af[3], b0a, b0b);
                MMA_F16(o[2*j+1][0], o[2*j+1][1], o[2*j+1][2], o[2*j+1][3],
                        af[0], af[1], af[2], af[3], b1a, b1b);
            }
        }
    }

    // ---- finalize: O / l, store ----
    __syncthreads();
    {
        float inv0 = 1.0f / l_s[wm + g];
        float inv1 = 1.0f / l_s[wm + 8 + g];
        float* ob = out + ((size_t)b * NT + q0) * NH;
        #pragma unroll
        for (int ni = 0; ni < 12; ni++) {
            int col = wnv + ni * 8 + t * 2;
            int row0 = wm + g;
            int row1 = wm + 8 + g;
            *(float2*)&ob[(size_t)row0 * NH + col] =
                make_float2(o[ni][0] * inv0, o[ni][1] * inv0);
            *(float2*)&ob[(size_t)row1 * NH + col] =
                make_float2(o[ni][2] * inv1, o[ni][3] * inv1);
        }
    }
}

// ============================================================================
// Launch
// ============================================================================
extern "C" void kernel_launch(void* const* d_in, const int* in_sizes, int n_in,
                              void* d_out, int out_size)
{
    const float* x  = (const float*)d_in[0];
    const float* Wq = (const float*)d_in[1];
    const float* Wk = (const float*)d_in[2];
    const float* Wv = (const float*)d_in[3];
    float* out = (float*)d_out;

    (void)in_sizes; (void)n_in; (void)out_size;

    // fp32 -> fp16 prepasses
    convert_x<<<(size_t)M_TOT * NC / (256 * 8), 256>>>(x);
    convert_w<<<3 * NC * NH / (256 * 8), 256>>>(Wq, Wk, Wv);

    // QKV projections (fp16 mma, 4-stage cp.async pipeline)
    cudaFuncSetAttribute(qkv_mma, cudaFuncAttributeMaxDynamicSharedMemorySize,
                         QKV_SMEM_BYTES);
    dim3 ggrd(M_TOT / GBM, 3);      // (512, 3)
    qkv_mma<<<ggrd, 256, QKV_SMEM_BYTES>>>();

    // Attention (fp16 mma)
    cudaFuncSetAttribute(attn_mma, cudaFuncAttributeMaxDynamicSharedMemorySize,
                         ATTN_SMEM_BYTES);
    dim3 agrd(NT / BQ, NB);         // (8, 64)
    attn_mma<<<agrd, 256, ATTN_SMEM_BYTES>>>(out);
}